// round 1
// baseline (speedup 1.0000x reference)
#include <cuda_runtime.h>
#include <math.h>

// Problem constants (fixed by the reference)
#define Bb    4
#define Tt    2048
#define Cc    1024
#define Hh    16
#define HDd   64
#define MROWS (Bb*Tt)      // 8192
#define THREEC (3*Cc)      // 3072

// Scratch (allocation-free rule: __device__ globals)
__device__ float g_qkv[(size_t)MROWS * THREEC];  // ~100 MB
__device__ float g_att[(size_t)MROWS * Cc];      // ~33 MB

// ---------------------------------------------------------------------------
// SGEMM:  Out[M,N] = A[M,K] (row-major) @ B[N,K]^T (row-major)  (+ bias)
// BM=BN=128, BK=16, 256 threads, 8x8 per-thread microtile.
// ---------------------------------------------------------------------------
template<bool HAS_BIAS>
__global__ __launch_bounds__(256)
void sgemm_nt(const float* __restrict__ A, const float* __restrict__ B,
              const float* __restrict__ bias, float* __restrict__ Out,
              int M, int N, int K)
{
    const int BM = 128, BN = 128, BK = 16;
    __shared__ float As[BK][BM];
    __shared__ float Bs[BK][BN];

    int tid = threadIdx.x;
    int bm = blockIdx.y * BM;
    int bn = blockIdx.x * BN;
    int tr = tid >> 4;        // 0..15
    int tc = tid & 15;        // 0..15

    float acc[8][8];
    #pragma unroll
    for (int i = 0; i < 8; i++)
        #pragma unroll
        for (int j = 0; j < 8; j++) acc[i][j] = 0.f;

    int lrow = tid >> 2;            // 0..63
    int lcol = (tid & 3) << 2;      // 0,4,8,12

    const float* Aptr = A + (size_t)(bm + lrow) * K + lcol;
    const float* Bptr = B + (size_t)(bn + lrow) * K + lcol;

    for (int k0 = 0; k0 < K; k0 += BK) {
        #pragma unroll
        for (int r = 0; r < 2; r++) {
            float4 va = *(const float4*)(Aptr + (size_t)(r * 64) * K + k0);
            As[lcol + 0][lrow + r * 64] = va.x;
            As[lcol + 1][lrow + r * 64] = va.y;
            As[lcol + 2][lrow + r * 64] = va.z;
            As[lcol + 3][lrow + r * 64] = va.w;
            float4 vb = *(const float4*)(Bptr + (size_t)(r * 64) * K + k0);
            Bs[lcol + 0][lrow + r * 64] = vb.x;
            Bs[lcol + 1][lrow + r * 64] = vb.y;
            Bs[lcol + 2][lrow + r * 64] = vb.z;
            Bs[lcol + 3][lrow + r * 64] = vb.w;
        }
        __syncthreads();

        #pragma unroll
        for (int k = 0; k < BK; k++) {
            float4 a0 = *(const float4*)&As[k][tr * 8];
            float4 a1 = *(const float4*)&As[k][tr * 8 + 4];
            float4 b0 = *(const float4*)&Bs[k][tc * 8];
            float4 b1 = *(const float4*)&Bs[k][tc * 8 + 4];
            float af[8] = {a0.x, a0.y, a0.z, a0.w, a1.x, a1.y, a1.z, a1.w};
            float bf[8] = {b0.x, b0.y, b0.z, b0.w, b1.x, b1.y, b1.z, b1.w};
            #pragma unroll
            for (int i = 0; i < 8; i++)
                #pragma unroll
                for (int j = 0; j < 8; j++)
                    acc[i][j] += af[i] * bf[j];
        }
        __syncthreads();
    }

    #pragma unroll
    for (int i = 0; i < 8; i++) {
        size_t row = (size_t)(bm + tr * 8 + i);
        #pragma unroll
        for (int j = 0; j < 8; j += 4) {
            int col = bn + tc * 8 + j;
            float4 v;
            v.x = acc[i][j];     v.y = acc[i][j + 1];
            v.z = acc[i][j + 2]; v.w = acc[i][j + 3];
            if (HAS_BIAS) {
                v.x += bias[col];     v.y += bias[col + 1];
                v.z += bias[col + 2]; v.w += bias[col + 3];
            }
            *(float4*)&Out[row * N + col] = v;
        }
    }
}

// ---------------------------------------------------------------------------
// Flash attention, fp32. One block = 64 queries of one (b,h).
// qkv layout per row: head h occupies cols [h*192, h*192+192): q|k|v each 64.
// Online softmax; causal tiles above diagonal skipped entirely.
// Smem: Qt/Kt are d-major (transposed) for conflict-free float4 frag loads.
// ---------------------------------------------------------------------------
#define LDP 68   // padded row length (multiple of 4 -> aligned float4)

__global__ __launch_bounds__(256)
void flash_attn(const float* __restrict__ qkv, float* __restrict__ out)
{
    extern __shared__ float smem[];
    float* Qt   = smem;                 // [64][LDP]  Qt[d][q]
    float* Kt   = Qt + 64 * LDP;        // [64][LDP]  Kt[d][k]
    float* Vs   = Kt + 64 * LDP;        // [64][LDP]  Vs[k][d]
    float* Ps   = Vs + 64 * LDP;        // [64][LDP]  scores / probs
    float* sm_m = Ps + 64 * LDP;        // [64]
    float* sm_l = sm_m + 64;            // [64]
    float* sm_a = sm_l + 64;            // [64]

    int bh  = blockIdx.x;               // 0..63
    int qt  = blockIdx.y;               // 0..31
    int b   = bh >> 4;
    int h   = bh & 15;
    int tid = threadIdx.x;
    int tr  = tid >> 4;                 // query group 0..15
    int tc  = tid & 15;                 // key/dim group 0..15

    const float scale = 0.125f;         // 1/sqrt(64)
    const float* base = qkv + (size_t)b * Tt * THREEC + h * (3 * HDd);

    // Load Q tile (transposed, pre-scaled)
    {
        const float* qbase = base + (size_t)(qt * 64) * THREEC;
        #pragma unroll
        for (int r = 0; r < 4; r++) {
            int f   = tid + 256 * r;          // 0..1023
            int row = f >> 4;                 // 0..63
            int col = (f & 15) << 2;          // 0..60
            float4 v = *(const float4*)(qbase + (size_t)row * THREEC + col);
            Qt[(col + 0) * LDP + row] = v.x * scale;
            Qt[(col + 1) * LDP + row] = v.y * scale;
            Qt[(col + 2) * LDP + row] = v.z * scale;
            Qt[(col + 3) * LDP + row] = v.w * scale;
        }
    }
    if (tid < 64) { sm_m[tid] = -INFINITY; sm_l[tid] = 0.f; }

    float o[4][4];
    #pragma unroll
    for (int i = 0; i < 4; i++)
        #pragma unroll
        for (int j = 0; j < 4; j++) o[i][j] = 0.f;

    __syncthreads();

    for (int kt = 0; kt <= qt; kt++) {
        // Load K (transposed) and V tiles
        const float* kbase = base + (size_t)(kt * 64) * THREEC + HDd;
        const float* vbase = kbase + HDd;
        #pragma unroll
        for (int r = 0; r < 4; r++) {
            int f   = tid + 256 * r;
            int row = f >> 4;
            int col = (f & 15) << 2;
            float4 kv = *(const float4*)(kbase + (size_t)row * THREEC + col);
            Kt[(col + 0) * LDP + row] = kv.x;
            Kt[(col + 1) * LDP + row] = kv.y;
            Kt[(col + 2) * LDP + row] = kv.z;
            Kt[(col + 3) * LDP + row] = kv.w;
            float4 vv = *(const float4*)(vbase + (size_t)row * THREEC + col);
            *(float4*)&Vs[row * LDP + col] = vv;
        }
        __syncthreads();

        // S = Q K^T  (each thread: 4x4)
        float s[4][4];
        #pragma unroll
        for (int i = 0; i < 4; i++)
            #pragma unroll
            for (int j = 0; j < 4; j++) s[i][j] = 0.f;

        #pragma unroll 8
        for (int d = 0; d < 64; d++) {
            float4 qv = *(const float4*)&Qt[d * LDP + tr * 4];
            float4 kv = *(const float4*)&Kt[d * LDP + tc * 4];
            float qa[4] = {qv.x, qv.y, qv.z, qv.w};
            float ka[4] = {kv.x, kv.y, kv.z, kv.w};
            #pragma unroll
            for (int i = 0; i < 4; i++)
                #pragma unroll
                for (int j = 0; j < 4; j++)
                    s[i][j] += qa[i] * ka[j];
        }

        if (kt == qt) {   // causal mask on diagonal tile
            #pragma unroll
            for (int i = 0; i < 4; i++) {
                int qr = tr * 4 + i;
                #pragma unroll
                for (int j = 0; j < 4; j++) {
                    if (tc * 4 + j > qr) s[i][j] = -INFINITY;
                }
            }
        }

        #pragma unroll
        for (int i = 0; i < 4; i++)
            *(float4*)&Ps[(tr * 4 + i) * LDP + tc * 4] =
                make_float4(s[i][0], s[i][1], s[i][2], s[i][3]);
        __syncthreads();

        // Online softmax row update (threads 0..63, one row each)
        if (tid < 64) {
            float mo = sm_m[tid];
            float rmax = mo;
            float* prow = Ps + tid * LDP;
            #pragma unroll 8
            for (int j = 0; j < 64; j++) rmax = fmaxf(rmax, prow[j]);
            float a = __expf(mo - rmax);
            float sum = 0.f;
            #pragma unroll 8
            for (int j = 0; j < 64; j++) {
                float p = __expf(prow[j] - rmax);
                prow[j] = p;
                sum += p;
            }
            sm_l[tid] = sm_l[tid] * a + sum;
            sm_m[tid] = rmax;
            sm_a[tid] = a;
        }
        __syncthreads();

        // O = O*alpha + P V
        float ar[4];
        #pragma unroll
        for (int i = 0; i < 4; i++) ar[i] = sm_a[tr * 4 + i];
        #pragma unroll
        for (int i = 0; i < 4; i++)
            #pragma unroll
            for (int j = 0; j < 4; j++) o[i][j] *= ar[i];

        #pragma unroll 4
        for (int kc = 0; kc < 64; kc += 4) {
            float pl[4][4];
            #pragma unroll
            for (int i = 0; i < 4; i++) {
                float4 p4 = *(const float4*)&Ps[(tr * 4 + i) * LDP + kc];
                pl[i][0] = p4.x; pl[i][1] = p4.y; pl[i][2] = p4.z; pl[i][3] = p4.w;
            }
            #pragma unroll
            for (int kk = 0; kk < 4; kk++) {
                float4 vv = *(const float4*)&Vs[(kc + kk) * LDP + tc * 4];
                float va[4] = {vv.x, vv.y, vv.z, vv.w};
                #pragma unroll
                for (int i = 0; i < 4; i++)
                    #pragma unroll
                    for (int j = 0; j < 4; j++)
                        o[i][j] += pl[i][kk] * va[j];
            }
        }
        __syncthreads();   // protect Kt/Vs/Ps before next tile load
    }

    // Normalize and write: out[b, t, h*64 + d]
    #pragma unroll
    for (int i = 0; i < 4; i++) {
        float inv = 1.f / sm_l[tr * 4 + i];
        size_t row = (size_t)b * Tt + (size_t)qt * 64 + tr * 4 + i;
        float4 v = make_float4(o[i][0] * inv, o[i][1] * inv,
                               o[i][2] * inv, o[i][3] * inv);
        *(float4*)&out[row * Cc + h * 64 + tc * 4] = v;
    }
}

// ---------------------------------------------------------------------------
extern "C" void kernel_launch(void* const* d_in, const int* in_sizes, int n_in,
                              void* d_out, int out_size)
{
    const float* x     = (const float*)d_in[0];  // [B,T,C]
    const float* Wqkv  = (const float*)d_in[1];  // [3C,C]
    const float* Wproj = (const float*)d_in[2];  // [C,C]
    const float* bproj = (const float*)d_in[3];  // [C]
    float* out = (float*)d_out;                  // [B,T,C]

    float *qkv_p, *att_p;
    cudaGetSymbolAddress((void**)&qkv_p, g_qkv);
    cudaGetSymbolAddress((void**)&att_p, g_att);

    // 1) QKV projection
    dim3 g1(THREEC / 128, MROWS / 128);
    sgemm_nt<false><<<g1, 256>>>(x, Wqkv, nullptr, qkv_p, MROWS, THREEC, Cc);

    // 2) Causal flash attention
    int smem_bytes = (4 * 64 * LDP + 3 * 64) * (int)sizeof(float);  // ~70.4 KB
    cudaFuncSetAttribute(flash_attn, cudaFuncAttributeMaxDynamicSharedMemorySize,
                         smem_bytes);
    flash_attn<<<dim3(Bb * Hh, Tt / 64), 256, smem_bytes>>>(qkv_p, att_p);

    // 3) Output projection (+bias)
    dim3 g3(Cc / 128, MROWS / 128);
    sgemm_nt<true><<<g3, 256>>>(att_p, Wproj, bproj, out, MROWS, Cc, Cc);
}